// round 12
// baseline (speedup 1.0000x reference)
#include <cuda_runtime.h>
#include <cstdint>

// probs: float32 [50,50,50,50] -> 6,250,000 floats (row-major)
// X:     int32   [8,000,000, 4]
// out:   float32 [8,000,000]
//
// out[i] = probs[ ((X0*50 + X1)*50 + X2)*50 + X3 ]
//
// R5/R10 structure (best measured: 43.8us profiled) + L2 eviction-priority
// via createpolicy + cache_hint (the width-legal encoding; bare L2::evict_*
// modifiers require .v8.b32 on sm_103a and were rejected by ptxas in R11):
//  - gathers: ld.global.nc.L2::cache_hint with evict_last policy
//             -> keep the 25MB probs table L2-resident
//  - X loads: evict_first policy (zero-reuse stream)
//  - stores:  evict_first policy (zero-reuse stream)
//  - quarter-warp predicated gathers (shorter replay chains), UNROLL=4.

constexpr int THREADS = 256;
constexpr int UNROLL  = 4;
constexpr int TILE    = THREADS * UNROLL;  // 1024 samples per block

__device__ __forceinline__ unsigned long long policy_evict_last()
{
    unsigned long long p;
    asm volatile("createpolicy.fractional.L2::evict_last.b64 %0, 1.0;" : "=l"(p));
    return p;
}

__device__ __forceinline__ unsigned long long policy_evict_first()
{
    unsigned long long p;
    asm volatile("createpolicy.fractional.L2::evict_first.b64 %0, 1.0;" : "=l"(p));
    return p;
}

__device__ __forceinline__ float ldg_hint(const float* p, unsigned long long pol)
{
    float v;
    asm volatile("ld.global.nc.L2::cache_hint.f32 %0, [%1], %2;"
                 : "=f"(v) : "l"(p), "l"(pol));
    return v;
}

__device__ __forceinline__ int4 ldg_v4_hint(const int4* p, unsigned long long pol)
{
    int4 v;
    asm volatile("ld.global.nc.L2::cache_hint.v4.s32 {%0,%1,%2,%3}, [%4], %5;"
                 : "=r"(v.x), "=r"(v.y), "=r"(v.z), "=r"(v.w) : "l"(p), "l"(pol));
    return v;
}

__device__ __forceinline__ void stg_hint(float* p, float v, unsigned long long pol)
{
    asm volatile("st.global.L2::cache_hint.f32 [%0], %1, %2;"
                 :: "l"(p), "f"(v), "l"(pol) : "memory");
}

__global__ __launch_bounds__(THREADS) void joint_cat_gather_pol(
    const float* __restrict__ probs,
    const int4* __restrict__ X,
    float* __restrict__ out,
    int n)
{
    const unsigned long long pol_last  = policy_evict_last();
    const unsigned long long pol_first = policy_evict_first();

    int base = blockIdx.x * TILE + threadIdx.x;
    int lane_group = (threadIdx.x & 31) >> 3;   // 0..3

    if (base + (UNROLL - 1) * THREADS < n) {
        // ---- fast path: full tile ----
        int4 x[UNROLL];
#pragma unroll
        for (int k = 0; k < UNROLL; k++)
            x[k] = ldg_v4_hint(&X[base + k * THREADS], pol_first);

        int idx[UNROLL];
#pragma unroll
        for (int k = 0; k < UNROLL; k++)
            idx[k] = ((x[k].x * 50 + x[k].y) * 50 + x[k].z) * 50 + x[k].w;

        float r[UNROLL];
        // 16 predicated gathers, 8 active lanes each, table pinned toward L2.
#pragma unroll
        for (int j = 0; j < 4; j++) {
#pragma unroll
            for (int k = 0; k < UNROLL; k++) {
                if (lane_group == j)
                    r[k] = ldg_hint(probs + idx[k], pol_last);
            }
        }

#pragma unroll
        for (int k = 0; k < UNROLL; k++)
            stg_hint(&out[base + k * THREADS], r[k], pol_first);
    } else {
        // ---- tail: per-element guard ----
#pragma unroll
        for (int k = 0; k < UNROLL; k++) {
            int i = base + k * THREADS;
            if (i < n) {
                int4 x = ldg_v4_hint(&X[i], pol_first);
                int idx = ((x.x * 50 + x.y) * 50 + x.z) * 50 + x.w;
                stg_hint(&out[i], ldg_hint(probs + idx, pol_last), pol_first);
            }
        }
    }
}

extern "C" void kernel_launch(void* const* d_in, const int* in_sizes, int n_in,
                              void* d_out, int out_size)
{
    const float* probs = (const float*)d_in[0];
    const int4* X = (const int4*)d_in[1];
    float* out = (float*)d_out;

    int n = out_size;  // 8,000,000 samples
    int blocks = (n + TILE - 1) / TILE;
    joint_cat_gather_pol<<<blocks, THREADS>>>(probs, X, out, n);
}

// round 13
// speedup vs baseline: 1.0358x; 1.0358x over previous
#include <cuda_runtime.h>
#include <cstdint>

// probs: float32 [50,50,50,50] -> 6,250,000 floats (row-major)
// X:     int32   [8,000,000, 4]
// out:   float32 [8,000,000]
//
// out[i] = probs[ ((X0*50 + X1)*50 + X2)*50 + X3 ]
//
// FINAL — best measured configuration across the full R2-R12 sweep
// (43.8us profiled, fastest of 11 variants):
//  - quarter-warp predicated gathers: 8 active lanes per LDG shortens each
//    instruction's divergent-address replay chain, letting L1tex pipeline
//    wavefronts across instructions (measured win R3->R4).
//  - __ldcg gathers (L2-only, no L1 fill/pollution), __ldcs X (streaming),
//    __stcs out (streaming)  (measured win R4->R5).
//  - UNROLL=4 at 24 regs -> ~90% occupancy; warp-parallelism > thread-ILP
//    here (UNROLL=8 at 34 regs / 68% occ measured strictly worse).
//  - Falsified levers (all neutral or worse): bulk-TMA X feed, persistent
//    double-buffered pipeline, cp.async gathers, L2 eviction-priority
//    policies. The ~44us level is the L1tex/L2 random-gather service floor:
//    8M gathers x 32B L2 sectors on top of the ~176MB DRAM stream floor.

constexpr int THREADS = 256;
constexpr int UNROLL  = 4;
constexpr int TILE    = THREADS * UNROLL;  // 1024 samples per block

__global__ __launch_bounds__(THREADS) void joint_cat_gather_final(
    const float* __restrict__ probs,
    const int4* __restrict__ X,
    float* __restrict__ out,
    int n)
{
    int base = blockIdx.x * TILE + threadIdx.x;
    int lane_group = (threadIdx.x & 31) >> 3;   // 0..3

    if (base + (UNROLL - 1) * THREADS < n) {
        // ---- fast path: full tile ----
        int4 x[UNROLL];
#pragma unroll
        for (int k = 0; k < UNROLL; k++)
            x[k] = __ldcs(&X[base + k * THREADS]);     // streaming coalesced 16B loads

        int idx[UNROLL];
#pragma unroll
        for (int k = 0; k < UNROLL; k++)
            idx[k] = ((x[k].x * 50 + x[k].y) * 50 + x[k].z) * 50 + x[k].w;

        float r[UNROLL];
        // 16 predicated LDG.cg, each with 8 active lanes.
#pragma unroll
        for (int j = 0; j < 4; j++) {
#pragma unroll
            for (int k = 0; k < UNROLL; k++) {
                if (lane_group == j)
                    r[k] = __ldcg(probs + idx[k]);     // L2-only gather, no L1 fill
            }
        }

#pragma unroll
        for (int k = 0; k < UNROLL; k++)
            __stcs(&out[base + k * THREADS], r[k]);    // streaming coalesced stores
    } else {
        // ---- tail: per-element guard ----
#pragma unroll
        for (int k = 0; k < UNROLL; k++) {
            int i = base + k * THREADS;
            if (i < n) {
                int4 x = __ldcs(&X[i]);
                int idx = ((x.x * 50 + x.y) * 50 + x.z) * 50 + x.w;
                __stcs(&out[i], __ldcg(probs + idx));
            }
        }
    }
}

extern "C" void kernel_launch(void* const* d_in, const int* in_sizes, int n_in,
                              void* d_out, int out_size)
{
    const float* probs = (const float*)d_in[0];
    const int4* X = (const int4*)d_in[1];
    float* out = (float*)d_out;

    int n = out_size;  // 8,000,000 samples
    int blocks = (n + TILE - 1) / TILE;
    joint_cat_gather_final<<<blocks, THREADS>>>(probs, X, out, n);
}